// round 8
// baseline (speedup 1.0000x reference)
#include <cuda_runtime.h>

#define Nq 32768
#define Mp 8192
#define C  128

// ---- grid knn config ----
#define G    32
#define NCELL (G*G*G)
#define Lr   6.0f
#define Hc   (2.0f*Lr/(float)G)    // 0.375
#define INVH ((float)G/(2.0f*Lr))
#define FBIG 3.4e38f

typedef unsigned long long ull;

union F2U { float2 f; ull u; };
__device__ __forceinline__ ull pk2(float a, float b){ F2U t; t.f.x=a; t.f.y=b; return t.u; }
__device__ __forceinline__ float lo2(ull v){ F2U t; t.u=v; return t.f.x; }
__device__ __forceinline__ float hi2(ull v){ F2U t; t.u=v; return t.f.y; }
__device__ __forceinline__ ull fma2(ull a, ull b, ull c){
    ull d; asm("fma.rn.f32x2 %0, %1, %2, %3;" : "=l"(d) : "l"(a), "l"(b), "l"(c)); return d;
}
__device__ __forceinline__ ull add2(ull a, ull b){
    ull d; asm("add.rn.f32x2 %0, %1, %2;" : "=l"(d) : "l"(a), "l"(b)); return d;
}

// stable top-3 insert with lexicographic (value, index) order — matches
// jax.lax.top_k tie semantics (lowest index wins on equal values) and makes
// the result independent of candidate visit order.
__device__ __forceinline__ void ins3i(float t, int idx,
                                      float& d0, float& d1, float& d2,
                                      int& i0, int& i1, int& i2)
{
    const bool b0 = (t < d0) || (t == d0 && idx < i0);
    const bool b1 = (t < d1) || (t == d1 && idx < i1);
    const bool b2 = (t < d2) || (t == d2 && idx < i2);
    d2 = b1 ? d1 : (b2 ? t : d2);
    i2 = b1 ? i1 : (b2 ? idx : i2);
    d1 = b0 ? d0 : (b1 ? t : d1);
    i1 = b0 ? i0 : (b1 ? idx : i1);
    d0 = b0 ? t : d0;
    i0 = b0 ? idx : i0;
}

// ---------------- scratch (device globals; no allocs allowed) ----------------
__device__ float4 g_wq[Nq];
__device__ int4   g_iq[Nq];
__device__ int    g_cnt[NCELL];
__device__ int    g_cellid[Mp];
__device__ int    g_off[NCELL+1];
__device__ int    g_woff[NCELL];
__device__ float4 g_pts[Mp];
__device__ int    g_pidx[Mp];
__device__ float  g_x0[Nq*C];
__device__ float  g_ya[Nq*C];
__device__ float  g_yb[Nq*C];
__device__ float  g_wt[3*C*C];
__device__ float  g_sum[C];
__device__ float  g_sq[C];
__device__ unsigned g_ctr;
__device__ float  g_ab[2*C];

extern __shared__ unsigned char s_raw[];

__device__ __forceinline__ int cell_coord(float x){
    int c = (int)floorf((x + Lr) * INVH);
    return min(G-1, max(0, c));
}

// ---------------- W transpose x3 in one launch ----------------
__global__ void __launch_bounds__(256,1) transpose3_kernel(const float* __restrict__ w0,
                                                           const float* __restrict__ w1,
                                                           const float* __restrict__ w2,
                                                           float* __restrict__ wt)
{
    const int b = blockIdx.x;                  // 192 blocks
    const float* w = (b < 64) ? w0 : ((b < 128) ? w1 : w2);
    const int local = (b & 63)*256 + threadIdx.x;   // 0..16383
    wt[(b >> 6)*16384 + local] = w[(local & 127)*128 + (local >> 7)];
}

// ---------------- grid build: count ----------------
__global__ void __launch_bounds__(256,1) cell_count_kernel(const float* __restrict__ pos2,
                                                           int* __restrict__ cnt,
                                                           int* __restrict__ cellid)
{
    const int i = blockIdx.x*256 + threadIdx.x;   // 32 blocks -> 8192
    const float x = pos2[3*i], y = pos2[3*i+1], z = pos2[3*i+2];
    const int cx = cell_coord(x), cy = cell_coord(y), cz = cell_coord(z);
    const int cell = (cz*G + cy)*G + cx;
    cellid[i] = cell;
    atomicAdd(&cnt[cell], 1);
}

// ---------------- grid build: prefix scan over 32768 cells ----------------
__global__ void __launch_bounds__(1024,1) scan_kernel(const int* __restrict__ cnt,
                                                      int* __restrict__ off,
                                                      int* __restrict__ woff)
{
    __shared__ int wsum[32];
    const int t = threadIdx.x;
    int local[32];
    int s = 0;
    #pragma unroll
    for (int i = 0; i < 32; i++){ local[i] = cnt[t*32 + i]; s += local[i]; }
    int v = s;
    #pragma unroll
    for (int d = 1; d < 32; d <<= 1){
        int u = __shfl_up_sync(0xffffffffu, v, d);
        if ((t & 31) >= d) v += u;
    }
    if ((t & 31) == 31) wsum[t >> 5] = v;
    __syncthreads();
    if (t < 32){
        int w = wsum[t];
        #pragma unroll
        for (int d = 1; d < 32; d <<= 1){
            int u = __shfl_up_sync(0xffffffffu, w, d);
            if (t >= d) w += u;
        }
        wsum[t] = w;
    }
    __syncthreads();
    int base = v - s + ((t >= 32) ? wsum[(t >> 5) - 1] : 0);
    #pragma unroll
    for (int i = 0; i < 32; i++){
        off[t*32 + i] = base;
        woff[t*32 + i] = base;
        base += local[i];
    }
    if (t == 1023) off[NCELL] = base;
}

// ---------------- grid build: scatter ----------------
__global__ void __launch_bounds__(256,1) scatter_kernel(const float* __restrict__ pos2,
                                                        const int* __restrict__ cellid,
                                                        int* __restrict__ woff,
                                                        float4* __restrict__ pts,
                                                        int* __restrict__ pidx)
{
    const int i = blockIdx.x*256 + threadIdx.x;   // 8192
    const int cell = cellid[i];
    const int slot = atomicAdd(&woff[cell], 1);
    const float x = pos2[3*i], y = pos2[3*i+1], z = pos2[3*i+2];
    pts[slot] = make_float4(x, y, z, x*x + y*y + z*z);
    pidx[slot] = i;
}

// ---------------- grid kNN: one thread per query, expanding rings ----------------
#define SCAN_RANGE(jb_, je_)                                                    \
    for (int j = (jb_); j < (je_); j++){                                        \
        const float4 cc = pts[j];                                               \
        const float tt = fmaf(m2x, cc.x, fmaf(m2y, cc.y, fmaf(m2z, cc.z, cc.w)));\
        if (tt <= t2v){ const int id = pidx[j]; ins3i(tt, id, t0, t1, t2v, i0, i1, i2); } \
    }

__global__ void __launch_bounds__(128,8) knn_grid_kernel(const float* __restrict__ pos1,
                                                         const float4* __restrict__ pts,
                                                         const int* __restrict__ pidx,
                                                         const int* __restrict__ off,
                                                         float4* __restrict__ wq,
                                                         int4* __restrict__ iq)
{
    const int n = blockIdx.x*128 + threadIdx.x;
    const float qx = pos1[3*n], qy = pos1[3*n+1], qz = pos1[3*n+2];
    const float n1 = qx*qx + qy*qy + qz*qz;
    const float m2x = -2.f*qx, m2y = -2.f*qy, m2z = -2.f*qz;
    const int cx = cell_coord(qx), cy = cell_coord(qy), cz = cell_coord(qz);

    float t0 = FBIG, t1 = FBIG, t2v = FBIG;
    int   i0 = 0x7fffffff, i1 = 0x7fffffff, i2 = 0x7fffffff;

    for (int r = 0; ; r++){
        const int xlo = max(cx - r, 0), xhi = min(cx + r, G-1);
        const int ylo = max(cy - r, 0), yhi = min(cy + r, G-1);
        const int zlo = max(cz - r, 0), zhi = min(cz + r, G-1);

        for (int z = zlo; z <= zhi; z++){
            const bool ze = (z == cz - r) || (z == cz + r);
            for (int y = ylo; y <= yhi; y++){
                const int rb = (z*G + y)*G;
                if (ze || (y == cy - r) || (y == cy + r)){
                    // full row [xlo..xhi] — contiguous point range
                    const int jb = off[rb + xlo];
                    const int je = off[rb + xhi + 1];
                    SCAN_RANGE(jb, je)
                } else {
                    const int xl = cx - r, xr = cx + r;
                    if (xl >= 0){
                        const int jb = off[rb + xl], je = off[rb + xl + 1];
                        SCAN_RANGE(jb, je)
                    }
                    if (xr <= G-1){
                        const int jb = off[rb + xr], je = off[rb + xr + 1];
                        SCAN_RANGE(jb, je)
                    }
                }
            }
        }

        // stop bound: unseen points are outside scanned box; their distance
        // >= min edge distance. Clamped/exhausted sides contribute +inf.
        const float bx0 = (xlo > 0)   ? (qx - ((float)xlo*Hc - Lr))       : FBIG;
        const float bx1 = (xhi < G-1) ? (((float)(xhi+1)*Hc - Lr) - qx)   : FBIG;
        const float by0 = (ylo > 0)   ? (qy - ((float)ylo*Hc - Lr))       : FBIG;
        const float by1 = (yhi < G-1) ? (((float)(yhi+1)*Hc - Lr) - qy)   : FBIG;
        const float bz0 = (zlo > 0)   ? (qz - ((float)zlo*Hc - Lr))       : FBIG;
        const float bz1 = (zhi < G-1) ? (((float)(zhi+1)*Hc - Lr) - qz)   : FBIG;
        const float dm = fminf(fminf(fminf(bx0, bx1), fminf(by0, by1)), fminf(bz0, bz1));
        if (t2v + n1 <= dm*dm) break;
    }

    const float a0 = fmaxf(t0 + n1, 0.f) + 1e-8f;
    const float a1 = fmaxf(t1 + n1, 0.f) + 1e-8f;
    const float a2 = fmaxf(t2v + n1, 0.f) + 1e-8f;
    const float w0 = 1.f/a0, w1 = 1.f/a1, w2 = 1.f/a2;
    const float inv = 1.f/(w0 + w1 + w2);
    wq[n] = make_float4(w0*inv, w1*inv, w2*inv, 0.f);
    iq[n] = make_int4(i0, i1, i2, 0);
}

// ---------------- interpolation: warp per point ----------------
__global__ void __launch_bounds__(256,1) interp_kernel(const float* __restrict__ feat2,
                                                       const float4* __restrict__ wq,
                                                       const int4*  __restrict__ iq,
                                                       float* __restrict__ x0)
{
    const int gw   = (blockIdx.x*256 + threadIdx.x) >> 5;
    const int lane = threadIdx.x & 31;
    const int4   id = iq[gw];
    const float4 w  = wq[gw];
    const float4* f4 = (const float4*)feat2;
    const float4 a = f4[id.x*32 + lane];
    const float4 b = f4[id.y*32 + lane];
    const float4 c = f4[id.z*32 + lane];
    float4 o;
    o.x = a.x*w.x + b.x*w.y + c.x*w.z;
    o.y = a.y*w.x + b.y*w.y + c.y*w.z;
    o.z = a.z*w.x + b.z*w.y + c.z*w.z;
    o.w = a.w*w.x + b.w*w.y + c.w*w.z;
    ((float4*)x0)[gw*32 + lane] = o;
}

// -- fused GEMM (+prev BN/ReLU on load) + BN-stat accumulation + last-block stats --
// 128x128 tile, 256 threads, 8x8 micro-tile (R4/R6-proven config)
__global__ void __launch_bounds__(256,1) gemm_bn_kernel(const float* __restrict__ x,
                                                        const float* __restrict__ wt,   // [k][j]
                                                        const float* __restrict__ bias,
                                                        const float* __restrict__ abin, // prev scale|shift or null
                                                        const float* __restrict__ g,
                                                        const float* __restrict__ be,
                                                        float* __restrict__ y,
                                                        float* __restrict__ gs,
                                                        float* __restrict__ gq,
                                                        unsigned* __restrict__ ctr,
                                                        float* __restrict__ about)
{
    float* Xs = (float*)s_raw;        // [128][132]
    float* Ws = Xs + 128*132;         // [128][128]
    const int t   = threadIdx.x;
    const int blk = blockIdx.x;

    {
        const float4* wt4 = (const float4*)wt;
        float4* ws4 = (float4*)Ws;
        #pragma unroll
        for (int i = 0; i < 16; i++) ws4[i*256 + t] = wt4[i*256 + t];
    }
    {
        const int lane = t & 31;
        const int rg   = t >> 5;
        float4 sc, sf;
        const bool aff = (abin != 0);
        if (aff){ sc = ((const float4*)abin)[lane]; sf = ((const float4*)abin)[32 + lane]; }
        const float4* x4 = (const float4*)x + (size_t)blk*(128*32);
        #pragma unroll
        for (int i = 0; i < 16; i++){
            const int r = rg + i*8;
            float4 v = x4[r*32 + lane];
            if (aff){
                v.x = fmaxf(fmaf(v.x, sc.x, sf.x), 0.f);
                v.y = fmaxf(fmaf(v.y, sc.y, sf.y), 0.f);
                v.z = fmaxf(fmaf(v.z, sc.z, sf.z), 0.f);
                v.w = fmaxf(fmaf(v.w, sc.w, sf.w), 0.f);
            }
            *(float4*)(Xs + r*132 + lane*4) = v;
        }
    }
    __syncthreads();

    const int tc = t & 15, tr = t >> 4;
    const int rbase = tr*8, cbase = tc*8;

    ull acc[8][4];
    {
        const ull b0 = pk2(bias[cbase+0], bias[cbase+1]);
        const ull b1 = pk2(bias[cbase+2], bias[cbase+3]);
        const ull b2 = pk2(bias[cbase+4], bias[cbase+5]);
        const ull b3 = pk2(bias[cbase+6], bias[cbase+7]);
        #pragma unroll
        for (int r = 0; r < 8; r++){ acc[r][0]=b0; acc[r][1]=b1; acc[r][2]=b2; acc[r][3]=b3; }
    }

    const float* xrow = Xs + rbase*132;
    #pragma unroll 4
    for (int k = 0; k < 128; k++){
        const float4 wa = *(const float4*)(Ws + k*128 + cbase);
        const float4 wb = *(const float4*)(Ws + k*128 + cbase + 4);
        const ull w0 = pk2(wa.x, wa.y), w1 = pk2(wa.z, wa.w);
        const ull w2 = pk2(wb.x, wb.y), w3 = pk2(wb.z, wb.w);
        #pragma unroll
        for (int r = 0; r < 8; r++){
            const float xv = xrow[r*132 + k];
            const ull xd = pk2(xv, xv);
            acc[r][0] = fma2(xd, w0, acc[r][0]);
            acc[r][1] = fma2(xd, w1, acc[r][1]);
            acc[r][2] = fma2(xd, w2, acc[r][2]);
            acc[r][3] = fma2(xd, w3, acc[r][3]);
        }
    }

    {
        float* yb = y + ((size_t)(blk*128 + rbase))*128 + cbase;
        #pragma unroll
        for (int r = 0; r < 8; r++){
            float4 o0, o1;
            o0.x = lo2(acc[r][0]); o0.y = hi2(acc[r][0]);
            o0.z = lo2(acc[r][1]); o0.w = hi2(acc[r][1]);
            o1.x = lo2(acc[r][2]); o1.y = hi2(acc[r][2]);
            o1.z = lo2(acc[r][3]); o1.w = hi2(acc[r][3]);
            *(float4*)(yb + r*128)     = o0;
            *(float4*)(yb + r*128 + 4) = o1;
        }
    }

    // per-block column sum / sumsq -> smem -> global atomics
    ull s4[4] = {0,0,0,0}, q4[4] = {0,0,0,0};
    #pragma unroll
    for (int r = 0; r < 8; r++){
        #pragma unroll
        for (int q = 0; q < 4; q++){
            s4[q] = add2(s4[q], acc[r][q]);
            q4[q] = fma2(acc[r][q], acc[r][q], q4[q]);
        }
    }
    __syncthreads();
    float* ps = (float*)s_raw;
    float* pq = ps + 16*128;
    #pragma unroll
    for (int q = 0; q < 4; q++){
        ps[tr*128 + cbase + 2*q]     = lo2(s4[q]);
        ps[tr*128 + cbase + 2*q + 1] = hi2(s4[q]);
        pq[tr*128 + cbase + 2*q]     = lo2(q4[q]);
        pq[tr*128 + cbase + 2*q + 1] = hi2(q4[q]);
    }
    __syncthreads();
    __shared__ unsigned s_last;
    if (t < 128){
        float ss = 0.f, qq = 0.f;
        #pragma unroll
        for (int i = 0; i < 16; i++){ ss += ps[i*128 + t]; qq += pq[i*128 + t]; }
        atomicAdd(&gs[t], ss);
        atomicAdd(&gq[t], qq);
    }
    __threadfence();
    __syncthreads();
    if (t == 0){
        const unsigned v = atomicInc(ctr, 255);   // wraps to 0 at old==255 (grid=256)
        s_last = (v == 255) ? 1u : 0u;
    }
    __syncthreads();
    if (s_last && t < 128){
        const float ss = atomicAdd(&gs[t], 0.f);  // coherent read
        const float qq = atomicAdd(&gq[t], 0.f);
        const float m  = ss * (1.f/32768.f);
        const float vv = qq * (1.f/32768.f) - m*m;
        const float sc = g[t] * rsqrtf(vv + 1e-5f);
        about[t]       = sc;
        about[128 + t] = be[t] - m*sc;
        gs[t] = 0.f;                              // reset for next gemm / next replay
        gq[t] = 0.f;
    }
}

// ---------------- final BN+ReLU to output ----------------
__global__ void __launch_bounds__(256,1) final_kernel(const float4* __restrict__ y,
                                                      const float* __restrict__ ab,
                                                      float4* __restrict__ out)
{
    const int i = blockIdx.x*256 + threadIdx.x;
    const int c = i & 31;
    const float4 sc = ((const float4*)ab)[c];
    const float4 sf = ((const float4*)ab)[32 + c];
    const float4 v = y[i];
    float4 o;
    o.x = fmaxf(fmaf(v.x, sc.x, sf.x), 0.f);
    o.y = fmaxf(fmaf(v.y, sc.y, sf.y), 0.f);
    o.z = fmaxf(fmaf(v.z, sc.z, sf.z), 0.f);
    o.w = fmaxf(fmaf(v.w, sc.w, sf.w), 0.f);
    out[i] = o;
}

// ---------------- launch ----------------
extern "C" void kernel_launch(void* const* d_in, const int* in_sizes, int n_in,
                              void* d_out, int out_size)
{
    const float* pos1  = (const float*)d_in[0];
    const float* pos2  = (const float*)d_in[1];
    const float* feat2 = (const float*)d_in[2];
    const float* Wm[3]  = {(const float*)d_in[3],  (const float*)d_in[7],  (const float*)d_in[11]};
    const float* bm[3]  = {(const float*)d_in[4],  (const float*)d_in[8],  (const float*)d_in[12]};
    const float* gm[3]  = {(const float*)d_in[5],  (const float*)d_in[9],  (const float*)d_in[13]};
    const float* bem[3] = {(const float*)d_in[6],  (const float*)d_in[10], (const float*)d_in[14]};

    float4 *wq, *pts; int4 *iq; float *x0, *ya, *yb, *gs, *gq, *ab, *wt;
    int *cnt, *cellid, *off, *woff, *pidx;
    unsigned* ctr;
    cudaGetSymbolAddress((void**)&wq, g_wq);
    cudaGetSymbolAddress((void**)&iq, g_iq);
    cudaGetSymbolAddress((void**)&cnt, g_cnt);
    cudaGetSymbolAddress((void**)&cellid, g_cellid);
    cudaGetSymbolAddress((void**)&off, g_off);
    cudaGetSymbolAddress((void**)&woff, g_woff);
    cudaGetSymbolAddress((void**)&pts, g_pts);
    cudaGetSymbolAddress((void**)&pidx, g_pidx);
    cudaGetSymbolAddress((void**)&x0, g_x0);
    cudaGetSymbolAddress((void**)&ya, g_ya);
    cudaGetSymbolAddress((void**)&yb, g_yb);
    cudaGetSymbolAddress((void**)&gs, g_sum);
    cudaGetSymbolAddress((void**)&gq, g_sq);
    cudaGetSymbolAddress((void**)&ctr, g_ctr);
    cudaGetSymbolAddress((void**)&ab, g_ab);
    cudaGetSymbolAddress((void**)&wt, g_wt);
    float* wts[3] = {wt, wt + 16384, wt + 32768};

    const int gemm_smem = (128*132 + 128*128) * 4;
    cudaFuncSetAttribute(gemm_bn_kernel, cudaFuncAttributeMaxDynamicSharedMemorySize, gemm_smem);

    transpose3_kernel<<<192,256>>>(Wm[0], Wm[1], Wm[2], wt);

    // grid build + query
    cudaMemsetAsync(cnt, 0, NCELL*sizeof(int), 0);
    cell_count_kernel<<<Mp/256,256>>>(pos2, cnt, cellid);
    scan_kernel<<<1,1024>>>(cnt, off, woff);
    scatter_kernel<<<Mp/256,256>>>(pos2, cellid, woff, pts, pidx);
    knn_grid_kernel<<<Nq/128,128>>>(pos1, pts, pidx, off, wq, iq);

    interp_kernel<<<4096,256>>>(feat2, wq, iq, x0);

    gemm_bn_kernel<<<256,256,gemm_smem>>>(x0, wts[0], bm[0], 0,  gm[0], bem[0], ya, gs, gq, ctr, ab);
    gemm_bn_kernel<<<256,256,gemm_smem>>>(ya, wts[1], bm[1], ab, gm[1], bem[1], yb, gs, gq, ctr, ab);
    gemm_bn_kernel<<<256,256,gemm_smem>>>(yb, wts[2], bm[2], ab, gm[2], bem[2], x0, gs, gq, ctr, ab);
    final_kernel<<<4096,256>>>((const float4*)x0, ab, (float4*)d_out);
}